// round 4
// baseline (speedup 1.0000x reference)
#include <cuda_runtime.h>
#include <math.h>

#define BB 32
#define SS 4096
#define DD 512          // INDIM == OUTDIM == 512
#define NCH 32
#define CS (SS / NCH)   // 128 keys per chunk

// ---- scratch (no allocations allowed) ----
__device__ float g_ht[BB * DD];          // 64 KB
__device__ float g_scores[BB * SS];      // 512 KB (raw masked scores)
__device__ float g_pm[BB * NCH];
__device__ float g_ps[BB * NCH];
__device__ float g_pc[BB * NCH * DD];    // 2 MB partial contexts
__device__ float g_cfin[BB * DD];

// memory_lengths may arrive as int32 or int64. Lengths are in [S/2, S] so the
// second 32-bit word is 0 iff the buffer is int64 (little-endian high word).
__device__ __forceinline__ int get_len(const int* __restrict__ L, int b) {
    return (L[1] == 0) ? L[2 * b] : L[b];
}

__device__ __forceinline__ float warp_allreduce_sum(float v) {
#pragma unroll
    for (int off = 16; off > 0; off >>= 1)
        v += __shfl_xor_sync(0xffffffffu, v, off);
    return v;
}

// ---------------------------------------------------------------------------
// Kernel 1: h_t[b][o] = dot(source[b,:], W_in[o,:])
// Warp-per-output; ALL 32 batches accumulated in registers (no per-batch
// shuffle chains, no block barriers). One smem-transpose reduce at the end.
// ---------------------------------------------------------------------------
__global__ void __launch_bounds__(256) k_ht(const float* __restrict__ src,
                                            const float* __restrict__ Win) {
    __shared__ float red[8][32][33];     // 33.8 KB, per-warp transpose pad
    int wid = threadIdx.x >> 5, lane = threadIdx.x & 31;
    int o = blockIdx.x * 8 + wid;        // 64 blocks x 8 warps = 512 outputs

    const float4* w4 = (const float4*)(Win + (size_t)o * DD);
    float4 w[4];
#pragma unroll
    for (int j = 0; j < 4; j++) w[j] = w4[lane + 32 * j];

    float acc[BB];
#pragma unroll
    for (int b = 0; b < BB; b++) acc[b] = 0.f;

#pragma unroll 4
    for (int b = 0; b < BB; b++) {
        const float4* x4 = (const float4*)(src + (size_t)b * DD);
#pragma unroll
        for (int j = 0; j < 4; j++) {
            float4 x = __ldg(&x4[lane + 32 * j]);
            acc[b] += w[j].x * x.x + w[j].y * x.y + w[j].z * x.z + w[j].w * x.w;
        }
    }

#pragma unroll
    for (int b = 0; b < BB; b++) red[wid][lane][b] = acc[b];
    __syncwarp();
    float tot = 0.f;
#pragma unroll
    for (int i = 0; i < 32; i++) tot += red[wid][i][lane];
    g_ht[lane * DD + o] = tot;           // lane == batch index
}

// ---------------------------------------------------------------------------
// Kernel 2: single-pass online-softmax attention over one (batch, chunk).
// Reads memory_bank exactly once — the HBM-bound kernel.
// Two keys per iteration (8 LDG.128 front-batched); rescale only on new max
// (scores are warp-uniform after allreduce -> branch is divergence-free).
// ---------------------------------------------------------------------------
__global__ void __launch_bounds__(256) k_attn(const float* __restrict__ mb,
                                              const int* __restrict__ L) {
    __shared__ float  cbuf[8][DD];   // 16 KB: per-warp scaled context
    __shared__ float2 ms[8];         // per-warp (m, sum)

    int b = blockIdx.y, chunk = blockIdx.x;
    int wid = threadIdx.x >> 5, lane = threadIdx.x & 31;
    int len = get_len(L, b);
    int s0 = chunk * CS;
    int send = min(s0 + CS, len);

    const float4* h4 = (const float4*)(g_ht + b * DD);
    float4 h[4];
#pragma unroll
    for (int j = 0; j < 4; j++) h[j] = h4[lane + 32 * j];

    float m = -INFINITY, ssum = 0.f;
    float4 c[4];
#pragma unroll
    for (int j = 0; j < 4; j++) c[j] = make_float4(0.f, 0.f, 0.f, 0.f);

    const float* bbase = mb + (size_t)b * SS * DD;
    int s = s0 + wid;

    for (; s + 8 < send; s += 16) {
        const float4* k4a = (const float4*)(bbase + (size_t)s * DD);
        const float4* k4b = (const float4*)(bbase + (size_t)(s + 8) * DD);
        float4 ka[4], kb[4];
#pragma unroll
        for (int j = 0; j < 4; j++) ka[j] = k4a[lane + 32 * j];
#pragma unroll
        for (int j = 0; j < 4; j++) kb[j] = k4b[lane + 32 * j];

        float da = 0.f, db = 0.f;
#pragma unroll
        for (int j = 0; j < 4; j++) {
            da += h[j].x * ka[j].x + h[j].y * ka[j].y
                + h[j].z * ka[j].z + h[j].w * ka[j].w;
            db += h[j].x * kb[j].x + h[j].y * kb[j].y
                + h[j].z * kb[j].z + h[j].w * kb[j].w;
        }
        float sa = warp_allreduce_sum(da);
        float sb = warp_allreduce_sum(db);
        if (lane == 0) {
            g_scores[b * SS + s]     = sa;
            g_scores[b * SS + s + 8] = sb;
        }

        float mx = fmaxf(sa, sb);
        if (mx <= m) {                       // common path: no rescale
            float pa = __expf(sa - m);
            float pb = __expf(sb - m);
            ssum += pa + pb;
#pragma unroll
            for (int j = 0; j < 4; j++) {
                c[j].x += pa * ka[j].x + pb * kb[j].x;
                c[j].y += pa * ka[j].y + pb * kb[j].y;
                c[j].z += pa * ka[j].z + pb * kb[j].z;
                c[j].w += pa * ka[j].w + pb * kb[j].w;
            }
        } else {                             // new max: rescale accumulators
            float sc = (m == -INFINITY) ? 0.f : __expf(m - mx);
            float pa = __expf(sa - mx);
            float pb = __expf(sb - mx);
            ssum = ssum * sc + pa + pb;
#pragma unroll
            for (int j = 0; j < 4; j++) {
                c[j].x = c[j].x * sc + pa * ka[j].x + pb * kb[j].x;
                c[j].y = c[j].y * sc + pa * ka[j].y + pb * kb[j].y;
                c[j].z = c[j].z * sc + pa * ka[j].z + pb * kb[j].z;
                c[j].w = c[j].w * sc + pa * ka[j].w + pb * kb[j].w;
            }
            m = mx;
        }
    }
    if (s < send) {                          // tail: at most one key per warp
        const float4* k4 = (const float4*)(bbase + (size_t)s * DD);
        float4 kv[4];
        float dot = 0.f;
#pragma unroll
        for (int j = 0; j < 4; j++) {
            kv[j] = k4[lane + 32 * j];
            dot += h[j].x * kv[j].x + h[j].y * kv[j].y
                 + h[j].z * kv[j].z + h[j].w * kv[j].w;
        }
        float score = warp_allreduce_sum(dot);
        if (lane == 0) g_scores[b * SS + s] = score;

        float mn = fmaxf(score, m);
        float sc = (m == -INFINITY) ? 0.f : __expf(m - mn);
        float p = __expf(score - mn);
        ssum = ssum * sc + p;
#pragma unroll
        for (int j = 0; j < 4; j++) {
            c[j].x = c[j].x * sc + p * kv[j].x;
            c[j].y = c[j].y * sc + p * kv[j].y;
            c[j].z = c[j].z * sc + p * kv[j].z;
            c[j].w = c[j].w * sc + p * kv[j].w;
        }
        m = mn;
    }

    if (lane == 0) ms[wid] = make_float2(m, ssum);
    __syncthreads();

    float M = -INFINITY;
#pragma unroll
    for (int w = 0; w < 8; w++) M = fmaxf(M, ms[w].x);

    float f = (m == -INFINITY) ? 0.f : __expf(m - M);
    float4* cb4 = (float4*)cbuf[wid];
#pragma unroll
    for (int j = 0; j < 4; j++) {
        float4 v = c[j];
        v.x *= f; v.y *= f; v.z *= f; v.w *= f;
        cb4[lane + 32 * j] = v;
    }
    __syncthreads();

    int pi = b * NCH + chunk;
    if (threadIdx.x == 0) {
        float Sc = 0.f;
#pragma unroll
        for (int w = 0; w < 8; w++) {
            float fm = ms[w].x;
            float fw = (fm == -INFINITY) ? 0.f : __expf(fm - M);
            Sc += ms[w].y * fw;
        }
        g_pm[pi] = M;
        g_ps[pi] = Sc;
    }
    // deterministic fixed-order cross-warp sum
    for (int d = threadIdx.x; d < DD; d += 256) {
        float acc = 0.f;
#pragma unroll
        for (int w = 0; w < 8; w++) acc += cbuf[w][d];
        g_pc[pi * DD + d] = acc;
    }
}

// ---------------------------------------------------------------------------
// Kernel 3: merge chunk partials -> final context; write align_vectors.
// grid (BB, 8): each y-part handles 1/8 of dims and 1/8 of positions.
// ---------------------------------------------------------------------------
__global__ void __launch_bounds__(256) k_reduce(const int* __restrict__ L,
                                                float* __restrict__ out) {
    int b = blockIdx.x, part = blockIdx.y;
    int len = get_len(L, b);

    float M = -INFINITY;
#pragma unroll
    for (int i = 0; i < NCH; i++) M = fmaxf(M, g_pm[b * NCH + i]);

    float e[NCH];
    float Ssum = 0.f;
#pragma unroll
    for (int i = 0; i < NCH; i++) {
        float mi = g_pm[b * NCH + i];
        e[i] = (mi == -INFINITY) ? 0.f : __expf(mi - M);
        Ssum += g_ps[b * NCH + i] * e[i];
    }
    float invS = 1.f / Ssum;

    if (threadIdx.x < DD / 8) {
        int d = part * (DD / 8) + threadIdx.x;
        float acc = 0.f;
#pragma unroll
        for (int i = 0; i < NCH; i++) acc += g_pc[(b * NCH + i) * DD + d] * e[i];
        g_cfin[b * DD + d] = acc * invS;
    }

    float* ali = out + BB * DD + (size_t)b * SS;
    int sbase = part * (SS / 8);
    for (int t = threadIdx.x; t < SS / 8; t += 256) {
        int s = sbase + t;
        ali[s] = (s < len) ? __expf(g_scores[b * SS + s] - M) * invS : 0.f;
    }
}

// ---------------------------------------------------------------------------
// Kernel 4: attn_h[b][o] = dot([c_final[b], source[b]], W_out[o,:])
// Warp-per-output; all 32 batches in register accumulators; W row (1024) in
// 8x float4 regs; x vectors stay L1-resident. Single end-of-kernel transpose
// reduce, no block barriers.
// ---------------------------------------------------------------------------
__global__ void __launch_bounds__(256) k_out(const float* __restrict__ src,
                                             const float* __restrict__ Wout,
                                             float* __restrict__ out) {
    __shared__ float red[8][32][33];     // 33.8 KB
    int wid = threadIdx.x >> 5, lane = threadIdx.x & 31;
    int o = blockIdx.x * 8 + wid;        // 64 blocks x 8 warps = 512 outputs

    const float4* w4 = (const float4*)(Wout + (size_t)o * (2 * DD)); // 256 f4
    float4 w[8];
#pragma unroll
    for (int j = 0; j < 8; j++) w[j] = w4[lane + 32 * j];

    float acc[BB];
#pragma unroll
    for (int b = 0; b < BB; b++) acc[b] = 0.f;

#pragma unroll 4
    for (int b = 0; b < BB; b++) {
        const float4* c4 = (const float4*)(g_cfin + (size_t)b * DD);
        const float4* s4 = (const float4*)(src + (size_t)b * DD);
        float d = 0.f;
#pragma unroll
        for (int j = 0; j < 4; j++) {
            float4 x = __ldg(&c4[lane + 32 * j]);
            d += w[j].x * x.x + w[j].y * x.y + w[j].z * x.z + w[j].w * x.w;
        }
#pragma unroll
        for (int j = 0; j < 4; j++) {
            float4 x = __ldg(&s4[lane + 32 * j]);
            d += w[4 + j].x * x.x + w[4 + j].y * x.y
               + w[4 + j].z * x.z + w[4 + j].w * x.w;
        }
        acc[b] = d;
    }

#pragma unroll
    for (int b = 0; b < BB; b++) red[wid][lane][b] = acc[b];
    __syncwarp();
    float tot = 0.f;
#pragma unroll
    for (int i = 0; i < 32; i++) tot += red[wid][i][lane];
    out[lane * DD + o] = tot;            // lane == batch index
}

// ---------------------------------------------------------------------------
extern "C" void kernel_launch(void* const* d_in, const int* in_sizes, int n_in,
                              void* d_out, int out_size) {
    const float* src  = (const float*)d_in[0];   // source        [32,1,512]
    const float* mb   = (const float*)d_in[1];   // memory_bank   [32,4096,512]
    const int*   L    = (const int*)  d_in[2];   // memory_lengths[32] (i32/i64)
    const float* Win  = (const float*)d_in[3];   // W_in          [512,512]
    const float* Wout = (const float*)d_in[4];   // W_out         [512,1024]
    float* out = (float*)d_out;                  // [32*512 attn_h | 32*4096 align]

    k_ht    <<<DD / 8, 256>>>(src, Win);
    k_attn  <<<dim3(NCH, BB), 256>>>(mb, L);
    k_reduce<<<dim3(BB, 8), 256>>>(L, out);
    k_out   <<<DD / 8, 256>>>(src, Wout, out);
}

// round 6
// speedup vs baseline: 1.3460x; 1.3460x over previous
#include <cuda_runtime.h>
#include <math.h>

#define BB 32
#define SS 4096
#define DD 512          // INDIM == OUTDIM == 512
#define NCH 32
#define CS (SS / NCH)   // 128 keys per chunk

// ---- scratch (no allocations allowed) ----
__device__ float g_ht[BB * DD];          // 64 KB
__device__ float g_scores[BB * SS];      // 512 KB (raw masked scores)
__device__ float g_pm[BB * NCH];
__device__ float g_ps[BB * NCH];
__device__ float g_pc[BB * NCH * DD];    // 2 MB partial contexts
__device__ float g_cfin[BB * DD];

// memory_lengths may arrive as int32 or int64. Lengths are in [S/2, S] so the
// second 32-bit word is 0 iff the buffer is int64 (little-endian high word).
__device__ __forceinline__ int get_len(const int* __restrict__ L, int b) {
    return (L[1] == 0) ? L[2 * b] : L[b];
}

__device__ __forceinline__ float warp_allreduce_sum(float v) {
#pragma unroll
    for (int off = 16; off > 0; off >>= 1)
        v += __shfl_xor_sync(0xffffffffu, v, off);
    return v;
}

// ---------------------------------------------------------------------------
// Kernel 1: h_t[b][o] = dot(source[b,:], W_in[o,:])
// grid (64, 4): 8 outputs x 8 batches per block. Warp = one output, 8 batch
// accumulators in regs. 2048 warps chip-wide; x vectors shared via L1.
// ---------------------------------------------------------------------------
__global__ void __launch_bounds__(256) k_ht(const float* __restrict__ src,
                                            const float* __restrict__ Win) {
    int wid = threadIdx.x >> 5, lane = threadIdx.x & 31;
    int o = blockIdx.x * 8 + wid;
    int b0 = blockIdx.y * 8;

    const float4* w4 = (const float4*)(Win + (size_t)o * DD);
    float4 w[4];
#pragma unroll
    for (int j = 0; j < 4; j++) w[j] = w4[lane + 32 * j];

    float acc[8];
#pragma unroll
    for (int i = 0; i < 8; i++) {
        const float4* x4 = (const float4*)(src + (size_t)(b0 + i) * DD);
        float d = 0.f;
#pragma unroll
        for (int j = 0; j < 4; j++) {
            float4 x = x4[lane + 32 * j];
            d += w[j].x * x.x + w[j].y * x.y + w[j].z * x.z + w[j].w * x.w;
        }
        acc[i] = d;
    }
#pragma unroll
    for (int i = 0; i < 8; i++) {
        float t = warp_allreduce_sum(acc[i]);
        if (lane == i) g_ht[(b0 + i) * DD + o] = t;
    }
}

// ---------------------------------------------------------------------------
// Kernel 2: single-pass online-softmax attention over one (batch, chunk).
// Reads memory_bank exactly once — the HBM-bound kernel.
// Two keys per iteration (8 LDG.128 front-batched); rescale only on new max
// (scores are warp-uniform after allreduce -> branch is divergence-free).
// ---------------------------------------------------------------------------
__global__ void __launch_bounds__(256) k_attn(const float* __restrict__ mb,
                                              const int* __restrict__ L) {
    __shared__ float  cbuf[8][DD];   // 16 KB: per-warp scaled context
    __shared__ float2 ms[8];         // per-warp (m, sum)

    int b = blockIdx.y, chunk = blockIdx.x;
    int wid = threadIdx.x >> 5, lane = threadIdx.x & 31;
    int len = get_len(L, b);
    int s0 = chunk * CS;
    int send = min(s0 + CS, len);

    const float4* h4 = (const float4*)(g_ht + b * DD);
    float4 h[4];
#pragma unroll
    for (int j = 0; j < 4; j++) h[j] = h4[lane + 32 * j];

    float m = -INFINITY, ssum = 0.f;
    float4 c[4];
#pragma unroll
    for (int j = 0; j < 4; j++) c[j] = make_float4(0.f, 0.f, 0.f, 0.f);

    const float* bbase = mb + (size_t)b * SS * DD;
    int s = s0 + wid;

    for (; s + 8 < send; s += 16) {
        const float4* k4a = (const float4*)(bbase + (size_t)s * DD);
        const float4* k4b = (const float4*)(bbase + (size_t)(s + 8) * DD);
        float4 ka[4], kb[4];
#pragma unroll
        for (int j = 0; j < 4; j++) ka[j] = k4a[lane + 32 * j];
#pragma unroll
        for (int j = 0; j < 4; j++) kb[j] = k4b[lane + 32 * j];

        float da = 0.f, db = 0.f;
#pragma unroll
        for (int j = 0; j < 4; j++) {
            da += h[j].x * ka[j].x + h[j].y * ka[j].y
                + h[j].z * ka[j].z + h[j].w * ka[j].w;
            db += h[j].x * kb[j].x + h[j].y * kb[j].y
                + h[j].z * kb[j].z + h[j].w * kb[j].w;
        }
        float sa = warp_allreduce_sum(da);
        float sb = warp_allreduce_sum(db);
        if (lane == 0) {
            g_scores[b * SS + s]     = sa;
            g_scores[b * SS + s + 8] = sb;
        }

        float mx = fmaxf(sa, sb);
        if (mx <= m) {                       // common path: no rescale
            float pa = __expf(sa - m);
            float pb = __expf(sb - m);
            ssum += pa + pb;
#pragma unroll
            for (int j = 0; j < 4; j++) {
                c[j].x += pa * ka[j].x + pb * kb[j].x;
                c[j].y += pa * ka[j].y + pb * kb[j].y;
                c[j].z += pa * ka[j].z + pb * kb[j].z;
                c[j].w += pa * ka[j].w + pb * kb[j].w;
            }
        } else {                             // new max: rescale accumulators
            float sc = (m == -INFINITY) ? 0.f : __expf(m - mx);
            float pa = __expf(sa - mx);
            float pb = __expf(sb - mx);
            ssum = ssum * sc + pa + pb;
#pragma unroll
            for (int j = 0; j < 4; j++) {
                c[j].x = c[j].x * sc + pa * ka[j].x + pb * kb[j].x;
                c[j].y = c[j].y * sc + pa * ka[j].y + pb * kb[j].y;
                c[j].z = c[j].z * sc + pa * ka[j].z + pb * kb[j].z;
                c[j].w = c[j].w * sc + pa * ka[j].w + pb * kb[j].w;
            }
            m = mx;
        }
    }
    if (s < send) {                          // tail: at most one key per warp
        const float4* k4 = (const float4*)(bbase + (size_t)s * DD);
        float4 kv[4];
        float dot = 0.f;
#pragma unroll
        for (int j = 0; j < 4; j++) {
            kv[j] = k4[lane + 32 * j];
            dot += h[j].x * kv[j].x + h[j].y * kv[j].y
                 + h[j].z * kv[j].z + h[j].w * kv[j].w;
        }
        float score = warp_allreduce_sum(dot);
        if (lane == 0) g_scores[b * SS + s] = score;

        float mn = fmaxf(score, m);
        float sc = (m == -INFINITY) ? 0.f : __expf(m - mn);
        float p = __expf(score - mn);
        ssum = ssum * sc + p;
#pragma unroll
        for (int j = 0; j < 4; j++) {
            c[j].x = c[j].x * sc + p * kv[j].x;
            c[j].y = c[j].y * sc + p * kv[j].y;
            c[j].z = c[j].z * sc + p * kv[j].z;
            c[j].w = c[j].w * sc + p * kv[j].w;
        }
        m = mn;
    }

    if (lane == 0) ms[wid] = make_float2(m, ssum);
    __syncthreads();

    float M = -INFINITY;
#pragma unroll
    for (int w = 0; w < 8; w++) M = fmaxf(M, ms[w].x);

    float f = (m == -INFINITY) ? 0.f : __expf(m - M);
    float4* cb4 = (float4*)cbuf[wid];
#pragma unroll
    for (int j = 0; j < 4; j++) {
        float4 v = c[j];
        v.x *= f; v.y *= f; v.z *= f; v.w *= f;
        cb4[lane + 32 * j] = v;
    }
    __syncthreads();

    int pi = b * NCH + chunk;
    if (threadIdx.x == 0) {
        float Sc = 0.f;
#pragma unroll
        for (int w = 0; w < 8; w++) {
            float fm = ms[w].x;
            float fw = (fm == -INFINITY) ? 0.f : __expf(fm - M);
            Sc += ms[w].y * fw;
        }
        g_pm[pi] = M;
        g_ps[pi] = Sc;
    }
    // deterministic fixed-order cross-warp sum
    for (int d = threadIdx.x; d < DD; d += 256) {
        float acc = 0.f;
#pragma unroll
        for (int w = 0; w < 8; w++) acc += cbuf[w][d];
        g_pc[pi * DD + d] = acc;
    }
}

// ---------------------------------------------------------------------------
// Kernel 3: merge chunk partials -> final context; write align_vectors.
// grid (BB, 8): each y-part handles 1/8 of dims and 1/8 of positions.
// ---------------------------------------------------------------------------
__global__ void __launch_bounds__(256) k_reduce(const int* __restrict__ L,
                                                float* __restrict__ out) {
    int b = blockIdx.x, part = blockIdx.y;
    int len = get_len(L, b);

    float M = -INFINITY;
#pragma unroll
    for (int i = 0; i < NCH; i++) M = fmaxf(M, g_pm[b * NCH + i]);

    float e[NCH];
    float Ssum = 0.f;
#pragma unroll
    for (int i = 0; i < NCH; i++) {
        float mi = g_pm[b * NCH + i];
        e[i] = (mi == -INFINITY) ? 0.f : __expf(mi - M);
        Ssum += g_ps[b * NCH + i] * e[i];
    }
    float invS = 1.f / Ssum;

    if (threadIdx.x < DD / 8) {
        int d = part * (DD / 8) + threadIdx.x;
        float acc = 0.f;
#pragma unroll
        for (int i = 0; i < NCH; i++) acc += g_pc[(b * NCH + i) * DD + d] * e[i];
        g_cfin[b * DD + d] = acc * invS;
    }

    float* ali = out + BB * DD + (size_t)b * SS;
    int sbase = part * (SS / 8);
    for (int t = threadIdx.x; t < SS / 8; t += 256) {
        int s = sbase + t;
        ali[s] = (s < len) ? __expf(g_scores[b * SS + s] - M) * invS : 0.f;
    }
}

// ---------------------------------------------------------------------------
// Kernel 4: attn_h[b][o] = dot([c_final[b], source[b]], W_out[o,:])
// grid (64, 4): 8 outputs x 8 batches per block. Warp = one output o with
// W row (1024) in 8x float4 regs; 8 batch accumulators (no spill). x vectors
// shared across the block's warps via L1. 2048 warps chip-wide.
// ---------------------------------------------------------------------------
__global__ void __launch_bounds__(256) k_out(const float* __restrict__ src,
                                             const float* __restrict__ Wout,
                                             float* __restrict__ out) {
    int wid = threadIdx.x >> 5, lane = threadIdx.x & 31;
    int o = blockIdx.x * 8 + wid;
    int b0 = blockIdx.y * 8;

    const float4* w4 = (const float4*)(Wout + (size_t)o * (2 * DD)); // 256 f4
    float4 w[8];
#pragma unroll
    for (int j = 0; j < 8; j++) w[j] = w4[lane + 32 * j];

    float acc[8];
#pragma unroll
    for (int i = 0; i < 8; i++) {
        int b = b0 + i;
        const float4* c4 = (const float4*)(g_cfin + (size_t)b * DD);
        const float4* s4 = (const float4*)(src + (size_t)b * DD);
        float d = 0.f;
#pragma unroll
        for (int j = 0; j < 4; j++) {
            float4 x = c4[lane + 32 * j];
            d += w[j].x * x.x + w[j].y * x.y + w[j].z * x.z + w[j].w * x.w;
        }
#pragma unroll
        for (int j = 0; j < 4; j++) {
            float4 x = s4[lane + 32 * j];
            d += w[4 + j].x * x.x + w[4 + j].y * x.y
               + w[4 + j].z * x.z + w[4 + j].w * x.w;
        }
        acc[i] = d;
    }
#pragma unroll
    for (int i = 0; i < 8; i++) {
        float t = warp_allreduce_sum(acc[i]);
        if (lane == i) out[(b0 + i) * DD + o] = t;
    }
}

// ---------------------------------------------------------------------------
extern "C" void kernel_launch(void* const* d_in, const int* in_sizes, int n_in,
                              void* d_out, int out_size) {
    const float* src  = (const float*)d_in[0];   // source        [32,1,512]
    const float* mb   = (const float*)d_in[1];   // memory_bank   [32,4096,512]
    const int*   L    = (const int*)  d_in[2];   // memory_lengths[32] (i32/i64)
    const float* Win  = (const float*)d_in[3];   // W_in          [512,512]
    const float* Wout = (const float*)d_in[4];   // W_out         [512,1024]
    float* out = (float*)d_out;                  // [32*512 attn_h | 32*4096 align]

    k_ht    <<<dim3(64, 4), 256>>>(src, Win);
    k_attn  <<<dim3(NCH, BB), 256>>>(mb, L);
    k_reduce<<<dim3(BB, 8), 256>>>(L, out);
    k_out   <<<dim3(64, 4), 256>>>(src, Wout, out);
}

// round 7
// speedup vs baseline: 1.4170x; 1.0528x over previous
#include <cuda_runtime.h>
#include <math.h>

#define BB 32
#define SS 4096
#define DD 512          // INDIM == OUTDIM == 512
#define NCH 32
#define CS (SS / NCH)   // 128 keys per chunk

// ---- scratch (no allocations allowed) ----
__device__ float g_ht[BB * DD];          // 64 KB
__device__ float g_scores[BB * SS];      // 512 KB (raw masked scores)
__device__ float g_pm[BB * NCH];
__device__ float g_ps[BB * NCH];
__device__ float g_pc[BB * NCH * DD];    // 2 MB partial contexts
__device__ float g_cfin[BB * DD];

// memory_lengths may arrive as int32 or int64. Lengths are in [S/2, S] so the
// second 32-bit word is 0 iff the buffer is int64 (little-endian high word).
__device__ __forceinline__ int get_len(const int* __restrict__ L, int b) {
    return (L[1] == 0) ? L[2 * b] : L[b];
}

__device__ __forceinline__ float warp_allreduce_sum(float v) {
#pragma unroll
    for (int off = 16; off > 0; off >>= 1)
        v += __shfl_xor_sync(0xffffffffu, v, off);
    return v;
}

// ---------------------------------------------------------------------------
// Kernel 1: h_t[b][o] = dot(source[b,:], W_in[o,:])
// grid (64, 8) = 512 blocks: warp = one output o, W row resident in 16 regs
// (launch_bounds(...,1) unlocks the register budget), 4 batch accumulators.
// 4096 warps chip-wide -> latency hidden; W_in L2 traffic 8 MB.
// ---------------------------------------------------------------------------
__global__ void __launch_bounds__(256, 1) k_ht(const float* __restrict__ src,
                                               const float* __restrict__ Win) {
    int wid = threadIdx.x >> 5, lane = threadIdx.x & 31;
    int o = blockIdx.x * 8 + wid;
    int b0 = blockIdx.y * 4;

    const float4* w4 = (const float4*)(Win + (size_t)o * DD);
    float4 w[4];
#pragma unroll
    for (int j = 0; j < 4; j++) w[j] = w4[lane + 32 * j];

    float acc[4];
#pragma unroll
    for (int i = 0; i < 4; i++) {
        const float4* x4 = (const float4*)(src + (size_t)(b0 + i) * DD);
        float d = 0.f;
#pragma unroll
        for (int j = 0; j < 4; j++) {
            float4 x = x4[lane + 32 * j];
            d += w[j].x * x.x + w[j].y * x.y + w[j].z * x.z + w[j].w * x.w;
        }
        acc[i] = d;
    }
#pragma unroll
    for (int i = 0; i < 4; i++) {
        float t = warp_allreduce_sum(acc[i]);
        if (lane == i) g_ht[(b0 + i) * DD + o] = t;
    }
}

// ---------------------------------------------------------------------------
// Kernel 2: single-pass online-softmax attention over one (batch, chunk).
// Reads memory_bank exactly once — the HBM-bound kernel.
// Two keys per iteration (8 LDG.128 front-batched); rescale only on new max
// (scores are warp-uniform after allreduce -> branch is divergence-free).
// ---------------------------------------------------------------------------
__global__ void __launch_bounds__(256) k_attn(const float* __restrict__ mb,
                                              const int* __restrict__ L) {
    __shared__ float  cbuf[8][DD];   // 16 KB: per-warp scaled context
    __shared__ float2 ms[8];         // per-warp (m, sum)

    int b = blockIdx.y, chunk = blockIdx.x;
    int wid = threadIdx.x >> 5, lane = threadIdx.x & 31;
    int len = get_len(L, b);
    int s0 = chunk * CS;
    int send = min(s0 + CS, len);

    const float4* h4 = (const float4*)(g_ht + b * DD);
    float4 h[4];
#pragma unroll
    for (int j = 0; j < 4; j++) h[j] = h4[lane + 32 * j];

    float m = -INFINITY, ssum = 0.f;
    float4 c[4];
#pragma unroll
    for (int j = 0; j < 4; j++) c[j] = make_float4(0.f, 0.f, 0.f, 0.f);

    const float* bbase = mb + (size_t)b * SS * DD;
    int s = s0 + wid;

    for (; s + 8 < send; s += 16) {
        const float4* k4a = (const float4*)(bbase + (size_t)s * DD);
        const float4* k4b = (const float4*)(bbase + (size_t)(s + 8) * DD);
        float4 ka[4], kb[4];
#pragma unroll
        for (int j = 0; j < 4; j++) ka[j] = k4a[lane + 32 * j];
#pragma unroll
        for (int j = 0; j < 4; j++) kb[j] = k4b[lane + 32 * j];

        float da = 0.f, db = 0.f;
#pragma unroll
        for (int j = 0; j < 4; j++) {
            da += h[j].x * ka[j].x + h[j].y * ka[j].y
                + h[j].z * ka[j].z + h[j].w * ka[j].w;
            db += h[j].x * kb[j].x + h[j].y * kb[j].y
                + h[j].z * kb[j].z + h[j].w * kb[j].w;
        }
        float sa = warp_allreduce_sum(da);
        float sb = warp_allreduce_sum(db);
        if (lane == 0) {
            g_scores[b * SS + s]     = sa;
            g_scores[b * SS + s + 8] = sb;
        }

        float mx = fmaxf(sa, sb);
        if (mx <= m) {                       // common path: no rescale
            float pa = __expf(sa - m);
            float pb = __expf(sb - m);
            ssum += pa + pb;
#pragma unroll
            for (int j = 0; j < 4; j++) {
                c[j].x += pa * ka[j].x + pb * kb[j].x;
                c[j].y += pa * ka[j].y + pb * kb[j].y;
                c[j].z += pa * ka[j].z + pb * kb[j].z;
                c[j].w += pa * ka[j].w + pb * kb[j].w;
            }
        } else {                             // new max: rescale accumulators
            float sc = (m == -INFINITY) ? 0.f : __expf(m - mx);
            float pa = __expf(sa - mx);
            float pb = __expf(sb - mx);
            ssum = ssum * sc + pa + pb;
#pragma unroll
            for (int j = 0; j < 4; j++) {
                c[j].x = c[j].x * sc + pa * ka[j].x + pb * kb[j].x;
                c[j].y = c[j].y * sc + pa * ka[j].y + pb * kb[j].y;
                c[j].z = c[j].z * sc + pa * ka[j].z + pb * kb[j].z;
                c[j].w = c[j].w * sc + pa * ka[j].w + pb * kb[j].w;
            }
            m = mx;
        }
    }
    if (s < send) {                          // tail: at most one key per warp
        const float4* k4 = (const float4*)(bbase + (size_t)s * DD);
        float4 kv[4];
        float dot = 0.f;
#pragma unroll
        for (int j = 0; j < 4; j++) {
            kv[j] = k4[lane + 32 * j];
            dot += h[j].x * kv[j].x + h[j].y * kv[j].y
                 + h[j].z * kv[j].z + h[j].w * kv[j].w;
        }
        float score = warp_allreduce_sum(dot);
        if (lane == 0) g_scores[b * SS + s] = score;

        float mn = fmaxf(score, m);
        float sc = (m == -INFINITY) ? 0.f : __expf(m - mn);
        float p = __expf(score - mn);
        ssum = ssum * sc + p;
#pragma unroll
        for (int j = 0; j < 4; j++) {
            c[j].x = c[j].x * sc + p * kv[j].x;
            c[j].y = c[j].y * sc + p * kv[j].y;
            c[j].z = c[j].z * sc + p * kv[j].z;
            c[j].w = c[j].w * sc + p * kv[j].w;
        }
        m = mn;
    }

    if (lane == 0) ms[wid] = make_float2(m, ssum);
    __syncthreads();

    float M = -INFINITY;
#pragma unroll
    for (int w = 0; w < 8; w++) M = fmaxf(M, ms[w].x);

    float f = (m == -INFINITY) ? 0.f : __expf(m - M);
    float4* cb4 = (float4*)cbuf[wid];
#pragma unroll
    for (int j = 0; j < 4; j++) {
        float4 v = c[j];
        v.x *= f; v.y *= f; v.z *= f; v.w *= f;
        cb4[lane + 32 * j] = v;
    }
    __syncthreads();

    int pi = b * NCH + chunk;
    if (threadIdx.x == 0) {
        float Sc = 0.f;
#pragma unroll
        for (int w = 0; w < 8; w++) {
            float fm = ms[w].x;
            float fw = (fm == -INFINITY) ? 0.f : __expf(fm - M);
            Sc += ms[w].y * fw;
        }
        g_pm[pi] = M;
        g_ps[pi] = Sc;
    }
    // deterministic fixed-order cross-warp sum
    for (int d = threadIdx.x; d < DD; d += 256) {
        float acc = 0.f;
#pragma unroll
        for (int w = 0; w < 8; w++) acc += cbuf[w][d];
        g_pc[pi * DD + d] = acc;
    }
}

// ---------------------------------------------------------------------------
// Kernel 3: merge chunk partials -> final context; write align_vectors.
// grid (BB, 8): each y-part handles 1/8 of dims and 1/8 of positions.
// ---------------------------------------------------------------------------
__global__ void __launch_bounds__(256) k_reduce(const int* __restrict__ L,
                                                float* __restrict__ out) {
    int b = blockIdx.x, part = blockIdx.y;
    int len = get_len(L, b);

    float M = -INFINITY;
#pragma unroll
    for (int i = 0; i < NCH; i++) M = fmaxf(M, g_pm[b * NCH + i]);

    float e[NCH];
    float Ssum = 0.f;
#pragma unroll
    for (int i = 0; i < NCH; i++) {
        float mi = g_pm[b * NCH + i];
        e[i] = (mi == -INFINITY) ? 0.f : __expf(mi - M);
        Ssum += g_ps[b * NCH + i] * e[i];
    }
    float invS = 1.f / Ssum;

    if (threadIdx.x < DD / 8) {
        int d = part * (DD / 8) + threadIdx.x;
        float acc = 0.f;
#pragma unroll
        for (int i = 0; i < NCH; i++) acc += g_pc[(b * NCH + i) * DD + d] * e[i];
        g_cfin[b * DD + d] = acc * invS;
    }

    float* ali = out + BB * DD + (size_t)b * SS;
    int sbase = part * (SS / 8);
    for (int t = threadIdx.x; t < SS / 8; t += 256) {
        int s = sbase + t;
        ali[s] = (s < len) ? __expf(g_scores[b * SS + s] - M) * invS : 0.f;
    }
}

// ---------------------------------------------------------------------------
// Kernel 4: attn_h[b][o] = dot([c_final[b], source[b]], W_out[o,:])
// grid (64, 8) = 512 blocks: warp = one output o, W row (1024) resident in
// 32 regs (launch_bounds(...,1) unlocks the budget), 4 batch accumulators.
// 4096 warps chip-wide; W_out L2 traffic 16 MB.
// ---------------------------------------------------------------------------
__global__ void __launch_bounds__(256, 1) k_out(const float* __restrict__ src,
                                                const float* __restrict__ Wout,
                                                float* __restrict__ out) {
    int wid = threadIdx.x >> 5, lane = threadIdx.x & 31;
    int o = blockIdx.x * 8 + wid;
    int b0 = blockIdx.y * 4;

    const float4* w4 = (const float4*)(Wout + (size_t)o * (2 * DD)); // 256 f4
    float4 w[8];
#pragma unroll
    for (int j = 0; j < 8; j++) w[j] = w4[lane + 32 * j];

    float acc[4];
#pragma unroll
    for (int i = 0; i < 4; i++) {
        int b = b0 + i;
        const float4* c4 = (const float4*)(g_cfin + (size_t)b * DD);
        const float4* s4 = (const float4*)(src + (size_t)b * DD);
        float d = 0.f;
#pragma unroll
        for (int j = 0; j < 4; j++) {
            float4 x = c4[lane + 32 * j];
            d += w[j].x * x.x + w[j].y * x.y + w[j].z * x.z + w[j].w * x.w;
        }
#pragma unroll
        for (int j = 0; j < 4; j++) {
            float4 x = s4[lane + 32 * j];
            d += w[4 + j].x * x.x + w[4 + j].y * x.y
               + w[4 + j].z * x.z + w[4 + j].w * x.w;
        }
        acc[i] = d;
    }
#pragma unroll
    for (int i = 0; i < 4; i++) {
        float t = warp_allreduce_sum(acc[i]);
        if (lane == i) out[(b0 + i) * DD + o] = t;
    }
}

// ---------------------------------------------------------------------------
extern "C" void kernel_launch(void* const* d_in, const int* in_sizes, int n_in,
                              void* d_out, int out_size) {
    const float* src  = (const float*)d_in[0];   // source        [32,1,512]
    const float* mb   = (const float*)d_in[1];   // memory_bank   [32,4096,512]
    const int*   L    = (const int*)  d_in[2];   // memory_lengths[32] (i32/i64)
    const float* Win  = (const float*)d_in[3];   // W_in          [512,512]
    const float* Wout = (const float*)d_in[4];   // W_out         [512,1024]
    float* out = (float*)d_out;                  // [32*512 attn_h | 32*4096 align]

    k_ht    <<<dim3(64, 8), 256>>>(src, Win);
    k_attn  <<<dim3(NCH, BB), 256>>>(mb, L);
    k_reduce<<<dim3(BB, 8), 256>>>(L, out);
    k_out   <<<dim3(64, 8), 256>>>(src, Wout, out);
}

// round 8
// speedup vs baseline: 1.4676x; 1.0357x over previous
#include <cuda_runtime.h>
#include <math.h>

#define BB 32
#define SS 4096
#define DD 512          // INDIM == OUTDIM == 512
#define NCH 32
#define CS (SS / NCH)   // 128 keys per chunk

// ---- scratch (no allocations allowed) ----
__device__ float g_ht[BB * DD];          // 64 KB
__device__ float g_scores[BB * SS];      // 512 KB (raw masked scores)
__device__ float g_pm[BB * NCH];
__device__ float g_ps[BB * NCH];
__device__ float g_pc[BB * NCH * DD];    // 2 MB partial contexts
__device__ float g_cfin[BB * DD];

// memory_lengths may arrive as int32 or int64. Lengths are in [S/2, S] so the
// second 32-bit word is 0 iff the buffer is int64 (little-endian high word).
__device__ __forceinline__ int get_len(const int* __restrict__ L, int b) {
    return (L[1] == 0) ? L[2 * b] : L[b];
}

__device__ __forceinline__ float warp_allreduce_sum(float v) {
#pragma unroll
    for (int off = 16; off > 0; off >>= 1)
        v += __shfl_xor_sync(0xffffffffu, v, off);
    return v;
}

// ---------------------------------------------------------------------------
// Kernel 1: h_t[b][o] = dot(source[b,:], W_in[o,:])
// grid (64, 8): warp = one output o, W row in 16 regs, 4 batch accumulators.
// launch_bounds(256,4) pins regs <= 64 -> 4 blocks/SM, occ 50%, W resident.
// ---------------------------------------------------------------------------
__global__ void __launch_bounds__(256, 4) k_ht(const float* __restrict__ src,
                                               const float* __restrict__ Win) {
    int wid = threadIdx.x >> 5, lane = threadIdx.x & 31;
    int o = blockIdx.x * 8 + wid;
    int b0 = blockIdx.y * 4;

    const float4* w4 = (const float4*)(Win + (size_t)o * DD);
    float4 w[4];
#pragma unroll
    for (int j = 0; j < 4; j++) w[j] = w4[lane + 32 * j];

    float acc[4];
#pragma unroll
    for (int i = 0; i < 4; i++) {
        const float4* x4 = (const float4*)(src + (size_t)(b0 + i) * DD);
        float d = 0.f;
#pragma unroll
        for (int j = 0; j < 4; j++) {
            float4 x = x4[lane + 32 * j];
            d += w[j].x * x.x + w[j].y * x.y + w[j].z * x.z + w[j].w * x.w;
        }
        acc[i] = d;
    }
#pragma unroll
    for (int i = 0; i < 4; i++) {
        float t = warp_allreduce_sum(acc[i]);
        if (lane == i) g_ht[(b0 + i) * DD + o] = t;
    }
}

// ---------------------------------------------------------------------------
// Kernel 2: single-pass online-softmax attention over one (batch, chunk).
// Reads memory_bank exactly once — the HBM-bound kernel.
// Two keys per iteration (8 LDG.128 front-batched); rescale only on new max
// (scores are warp-uniform after allreduce -> branch is divergence-free).
// ---------------------------------------------------------------------------
__global__ void __launch_bounds__(256) k_attn(const float* __restrict__ mb,
                                              const int* __restrict__ L) {
    __shared__ float  cbuf[8][DD];   // 16 KB: per-warp scaled context
    __shared__ float2 ms[8];         // per-warp (m, sum)

    int b = blockIdx.y, chunk = blockIdx.x;
    int wid = threadIdx.x >> 5, lane = threadIdx.x & 31;
    int len = get_len(L, b);
    int s0 = chunk * CS;
    int send = min(s0 + CS, len);

    const float4* h4 = (const float4*)(g_ht + b * DD);
    float4 h[4];
#pragma unroll
    for (int j = 0; j < 4; j++) h[j] = h4[lane + 32 * j];

    float m = -INFINITY, ssum = 0.f;
    float4 c[4];
#pragma unroll
    for (int j = 0; j < 4; j++) c[j] = make_float4(0.f, 0.f, 0.f, 0.f);

    const float* bbase = mb + (size_t)b * SS * DD;
    int s = s0 + wid;

    for (; s + 8 < send; s += 16) {
        const float4* k4a = (const float4*)(bbase + (size_t)s * DD);
        const float4* k4b = (const float4*)(bbase + (size_t)(s + 8) * DD);
        float4 ka[4], kb[4];
#pragma unroll
        for (int j = 0; j < 4; j++) ka[j] = k4a[lane + 32 * j];
#pragma unroll
        for (int j = 0; j < 4; j++) kb[j] = k4b[lane + 32 * j];

        float da = 0.f, db = 0.f;
#pragma unroll
        for (int j = 0; j < 4; j++) {
            da += h[j].x * ka[j].x + h[j].y * ka[j].y
                + h[j].z * ka[j].z + h[j].w * ka[j].w;
            db += h[j].x * kb[j].x + h[j].y * kb[j].y
                + h[j].z * kb[j].z + h[j].w * kb[j].w;
        }
        float sa = warp_allreduce_sum(da);
        float sb = warp_allreduce_sum(db);
        if (lane == 0) {
            g_scores[b * SS + s]     = sa;
            g_scores[b * SS + s + 8] = sb;
        }

        float mx = fmaxf(sa, sb);
        if (mx <= m) {                       // common path: no rescale
            float pa = __expf(sa - m);
            float pb = __expf(sb - m);
            ssum += pa + pb;
#pragma unroll
            for (int j = 0; j < 4; j++) {
                c[j].x += pa * ka[j].x + pb * kb[j].x;
                c[j].y += pa * ka[j].y + pb * kb[j].y;
                c[j].z += pa * ka[j].z + pb * kb[j].z;
                c[j].w += pa * ka[j].w + pb * kb[j].w;
            }
        } else {                             // new max: rescale accumulators
            float sc = (m == -INFINITY) ? 0.f : __expf(m - mx);
            float pa = __expf(sa - mx);
            float pb = __expf(sb - mx);
            ssum = ssum * sc + pa + pb;
#pragma unroll
            for (int j = 0; j < 4; j++) {
                c[j].x = c[j].x * sc + pa * ka[j].x + pb * kb[j].x;
                c[j].y = c[j].y * sc + pa * ka[j].y + pb * kb[j].y;
                c[j].z = c[j].z * sc + pa * ka[j].z + pb * kb[j].z;
                c[j].w = c[j].w * sc + pa * ka[j].w + pb * kb[j].w;
            }
            m = mx;
        }
    }
    if (s < send) {                          // tail: at most one key per warp
        const float4* k4 = (const float4*)(bbase + (size_t)s * DD);
        float4 kv[4];
        float dot = 0.f;
#pragma unroll
        for (int j = 0; j < 4; j++) {
            kv[j] = k4[lane + 32 * j];
            dot += h[j].x * kv[j].x + h[j].y * kv[j].y
                 + h[j].z * kv[j].z + h[j].w * kv[j].w;
        }
        float score = warp_allreduce_sum(dot);
        if (lane == 0) g_scores[b * SS + s] = score;

        float mn = fmaxf(score, m);
        float sc = (m == -INFINITY) ? 0.f : __expf(m - mn);
        float p = __expf(score - mn);
        ssum = ssum * sc + p;
#pragma unroll
        for (int j = 0; j < 4; j++) {
            c[j].x = c[j].x * sc + p * kv[j].x;
            c[j].y = c[j].y * sc + p * kv[j].y;
            c[j].z = c[j].z * sc + p * kv[j].z;
            c[j].w = c[j].w * sc + p * kv[j].w;
        }
        m = mn;
    }

    if (lane == 0) ms[wid] = make_float2(m, ssum);
    __syncthreads();

    float M = -INFINITY;
#pragma unroll
    for (int w = 0; w < 8; w++) M = fmaxf(M, ms[w].x);

    float f = (m == -INFINITY) ? 0.f : __expf(m - M);
    float4* cb4 = (float4*)cbuf[wid];
#pragma unroll
    for (int j = 0; j < 4; j++) {
        float4 v = c[j];
        v.x *= f; v.y *= f; v.z *= f; v.w *= f;
        cb4[lane + 32 * j] = v;
    }
    __syncthreads();

    int pi = b * NCH + chunk;
    if (threadIdx.x == 0) {
        float Sc = 0.f;
#pragma unroll
        for (int w = 0; w < 8; w++) {
            float fm = ms[w].x;
            float fw = (fm == -INFINITY) ? 0.f : __expf(fm - M);
            Sc += ms[w].y * fw;
        }
        g_pm[pi] = M;
        g_ps[pi] = Sc;
    }
    // deterministic fixed-order cross-warp sum
    for (int d = threadIdx.x; d < DD; d += 256) {
        float acc = 0.f;
#pragma unroll
        for (int w = 0; w < 8; w++) acc += cbuf[w][d];
        g_pc[pi * DD + d] = acc;
    }
}

// ---------------------------------------------------------------------------
// Kernel 3: merge chunk partials -> final context; write align_vectors.
// grid (BB, 8): each y-part handles 1/8 of dims and 1/8 of positions.
// ---------------------------------------------------------------------------
__global__ void __launch_bounds__(256) k_reduce(const int* __restrict__ L,
                                                float* __restrict__ out) {
    int b = blockIdx.x, part = blockIdx.y;
    int len = get_len(L, b);

    float M = -INFINITY;
#pragma unroll
    for (int i = 0; i < NCH; i++) M = fmaxf(M, g_pm[b * NCH + i]);

    float e[NCH];
    float Ssum = 0.f;
#pragma unroll
    for (int i = 0; i < NCH; i++) {
        float mi = g_pm[b * NCH + i];
        e[i] = (mi == -INFINITY) ? 0.f : __expf(mi - M);
        Ssum += g_ps[b * NCH + i] * e[i];
    }
    float invS = 1.f / Ssum;

    if (threadIdx.x < DD / 8) {
        int d = part * (DD / 8) + threadIdx.x;
        float acc = 0.f;
#pragma unroll
        for (int i = 0; i < NCH; i++) acc += g_pc[(b * NCH + i) * DD + d] * e[i];
        g_cfin[b * DD + d] = acc * invS;
    }

    float* ali = out + BB * DD + (size_t)b * SS;
    int sbase = part * (SS / 8);
    for (int t = threadIdx.x; t < SS / 8; t += 256) {
        int s = sbase + t;
        ali[s] = (s < len) ? __expf(g_scores[b * SS + s] - M) * invS : 0.f;
    }
}

// ---------------------------------------------------------------------------
// Kernel 4: attn_h[b][o] = dot([c_final[b], source[b]], W_out[o,:])
// grid (64, 8): warp = one output o, W row (1024) in 32 regs, 4 batch
// accumulators. launch_bounds(256,4) pins regs <= 64 -> 4 blocks/SM, occ 50%,
// W resident AND latency hidden (the R4-R7 versions each had only one).
// ---------------------------------------------------------------------------
__global__ void __launch_bounds__(256, 4) k_out(const float* __restrict__ src,
                                                const float* __restrict__ Wout,
                                                float* __restrict__ out) {
    int wid = threadIdx.x >> 5, lane = threadIdx.x & 31;
    int o = blockIdx.x * 8 + wid;
    int b0 = blockIdx.y * 4;

    const float4* w4 = (const float4*)(Wout + (size_t)o * (2 * DD)); // 256 f4
    float4 w[8];
#pragma unroll
    for (int j = 0; j < 8; j++) w[j] = w4[lane + 32 * j];

    float acc[4];
#pragma unroll
    for (int i = 0; i < 4; i++) {
        int b = b0 + i;
        const float4* c4 = (const float4*)(g_cfin + (size_t)b * DD);
        const float4* s4 = (const float4*)(src + (size_t)b * DD);
        float d = 0.f;
#pragma unroll
        for (int j = 0; j < 4; j++) {
            float4 x = c4[lane + 32 * j];
            d += w[j].x * x.x + w[j].y * x.y + w[j].z * x.z + w[j].w * x.w;
        }
#pragma unroll
        for (int j = 0; j < 4; j++) {
            float4 x = s4[lane + 32 * j];
            d += w[4 + j].x * x.x + w[4 + j].y * x.y
               + w[4 + j].z * x.z + w[4 + j].w * x.w;
        }
        acc[i] = d;
    }
#pragma unroll
    for (int i = 0; i < 4; i++) {
        float t = warp_allreduce_sum(acc[i]);
        if (lane == i) out[(b0 + i) * DD + o] = t;
    }
}

// ---------------------------------------------------------------------------
extern "C" void kernel_launch(void* const* d_in, const int* in_sizes, int n_in,
                              void* d_out, int out_size) {
    const float* src  = (const float*)d_in[0];   // source        [32,1,512]
    const float* mb   = (const float*)d_in[1];   // memory_bank   [32,4096,512]
    const int*   L    = (const int*)  d_in[2];   // memory_lengths[32] (i32/i64)
    const float* Win  = (const float*)d_in[3];   // W_in          [512,512]
    const float* Wout = (const float*)d_in[4];   // W_out         [512,1024]
    float* out = (float*)d_out;                  // [32*512 attn_h | 32*4096 align]

    k_ht    <<<dim3(64, 8), 256>>>(src, Win);
    k_attn  <<<dim3(NCH, BB), 256>>>(mb, L);
    k_reduce<<<dim3(BB, 8), 256>>>(L, out);
    k_out   <<<dim3(64, 8), 256>>>(src, Wout, out);
}